// round 1
// baseline (speedup 1.0000x reference)
#include <cuda_runtime.h>
#include <math.h>

#define NN 50000
#define EE 800000
#define HH 4
#define CC 64
#define HC 256
#define FEAT 128
#define EDIM 16
#define GG 256
#define NEG 0.2f
#define BNEPS 1e-5f

// ---------------- device scratch (no allocs allowed) ----------------
__device__ float  g_h[(size_t)NN * HC];
__device__ float  g_bufA[(size_t)NN * HC];
__device__ float  g_bufB[(size_t)NN * HC];
__device__ float  g_ssrc[NN * HH];
__device__ float  g_sdst[NN * HH];
__device__ float  g_alphaE[(size_t)EE * HH];
__device__ int    g_deg[NN];
__device__ int    g_rowptr[NN + 1];
__device__ int    g_cursor[NN];
__device__ int    g_csrc[EE];
__device__ int    g_ceid[EE];
__device__ float  g_meanEA[EDIM];
__device__ float  g_M[EDIM * HH];
__device__ float  g_selfAE[HH];
__device__ double g_bnsum[HC];
__device__ double g_bnsq[HC];
__device__ float  g_scale[HC];
__device__ float  g_shift[HC];
__device__ float  g_pool[GG * HC];
__device__ float  g_cnt[GG];

__device__ __forceinline__ float lrelu(float x) { return x > 0.f ? x : NEG * x; }

// ---------------- init / CSR build ----------------
__global__ void k_init() {
    int i = blockIdx.x * 256 + threadIdx.x;
    if (i < NN) g_deg[i] = 0;
    if (i < EDIM) g_meanEA[i] = 0.f;
    if (i < GG * HC) g_pool[i] = 0.f;
    if (i < GG) g_cnt[i] = 0.f;
}

__global__ void k_hist(const int* __restrict__ dst) {
    int e = blockIdx.x * 256 + threadIdx.x;
    if (e < EE) atomicAdd(&g_deg[dst[e]], 1);
}

__global__ void k_scan() {
    __shared__ int part[1024];
    int t = threadIdx.x;
    const int per = (NN + 1023) / 1024;
    int base = t * per;
    int s = 0;
    for (int i = 0; i < per; i++) {
        int idx = base + i;
        if (idx < NN) s += g_deg[idx];
    }
    part[t] = s;
    __syncthreads();
    for (int off = 1; off < 1024; off <<= 1) {
        int v = (t >= off) ? part[t - off] : 0;
        __syncthreads();
        part[t] += v;
        __syncthreads();
    }
    int run = (t == 0) ? 0 : part[t - 1];
    for (int i = 0; i < per; i++) {
        int idx = base + i;
        if (idx < NN) {
            g_rowptr[idx] = run;
            g_cursor[idx] = run;
            run += g_deg[idx];
        }
    }
    if (t == 1023) g_rowptr[NN] = run;
}

__global__ void k_scatter(const int* __restrict__ src, const int* __restrict__ dst) {
    int e = blockIdx.x * 256 + threadIdx.x;
    if (e < EE) {
        int d = dst[e];
        int p = atomicAdd(&g_cursor[d], 1);
        g_csrc[p] = src[e];
        g_ceid[p] = e;
    }
}

// ---------------- edge-feature attention (collapsed) ----------------
__global__ void k_ea_sum(const float* __restrict__ ea) {
    __shared__ float sm[256];
    int t = threadIdx.x;
    size_t stride = (size_t)gridDim.x * 256;
    float s = 0.f;
    for (size_t i = (size_t)blockIdx.x * 256 + t; i < (size_t)EE * EDIM; i += stride)
        s += ea[i];
    sm[t] = s;
    __syncthreads();
    if (t < 16) {
        float a = 0.f;
        for (int k = t; k < 256; k += 16) a += sm[k];
        atomicAdd(&g_meanEA[t], a);
    }
}

__global__ void k_M(const float* __restrict__ We, const float* __restrict__ ae) {
    int t = threadIdx.x;  // 64 threads
    int d = t >> 2, hh = t & 3;
    float s = 0.f;
    for (int c = 0; c < CC; c++)
        s += We[d * HC + hh * CC + c] * ae[hh * CC + c];
    g_M[d * HH + hh] = s;
    __syncthreads();
    if (t < HH) {
        float s2 = 0.f;
        for (int d2 = 0; d2 < EDIM; d2++)
            s2 += (g_meanEA[d2] / (float)EE) * g_M[d2 * HH + t];
        g_selfAE[t] = s2;
    }
}

__global__ void k_alphaE(const float* __restrict__ ea) {
    __shared__ float M[EDIM * HH];
    if (threadIdx.x < EDIM * HH) M[threadIdx.x] = g_M[threadIdx.x];
    __syncthreads();
    int e = blockIdx.x * 256 + threadIdx.x;
    if (e >= EE) return;
    const float* row = ea + (size_t)e * EDIM;
    float a0 = 0.f, a1 = 0.f, a2 = 0.f, a3 = 0.f;
#pragma unroll
    for (int d = 0; d < EDIM; d++) {
        float v = row[d];
        a0 += v * M[d * 4 + 0];
        a1 += v * M[d * 4 + 1];
        a2 += v * M[d * 4 + 2];
        a3 += v * M[d * 4 + 3];
    }
    *(float4*)&g_alphaE[(size_t)e * 4] = make_float4(a0, a1, a2, a3);
}

// ---------------- SGEMM: C[N,256] = A[N,K] @ B[K,256] ----------------
#define BM 128
#define BN 64
#define BK 16
#define TM 8
#define TN 4
__global__ __launch_bounds__(256) void k_sgemm(const float* __restrict__ A,
                                               const float* __restrict__ B,
                                               float* __restrict__ C, int K) {
    __shared__ float As[BK][BM];
    __shared__ float Bs[BK][BN];
    int tid = threadIdx.x;
    int tx = tid % 16;
    int ty = tid / 16;
    int rowBase = blockIdx.y * BM;
    int colBase = blockIdx.x * BN;
    int arow0 = tid / 4;
    int af = tid % 4;
    int brow = tid / 16;
    int bf = tid % 16;
    float acc[TM][TN] = {};
    for (int k0 = 0; k0 < K; k0 += BK) {
#pragma unroll
        for (int rr = 0; rr < 2; rr++) {
            int r = arow0 + rr * 64;
            int grow = rowBase + r;
            float4 v = (grow < NN) ? *(const float4*)(A + (size_t)grow * K + k0 + af * 4)
                                   : make_float4(0.f, 0.f, 0.f, 0.f);
            As[af * 4 + 0][r] = v.x;
            As[af * 4 + 1][r] = v.y;
            As[af * 4 + 2][r] = v.z;
            As[af * 4 + 3][r] = v.w;
        }
        {
            float4 v = *(const float4*)(B + (size_t)(k0 + brow) * HC + colBase + bf * 4);
            *(float4*)&Bs[brow][bf * 4] = v;
        }
        __syncthreads();
#pragma unroll
        for (int kk = 0; kk < BK; kk++) {
            float ra[TM], rb[TN];
#pragma unroll
            for (int i = 0; i < TM; i++) ra[i] = As[kk][ty * TM + i];
#pragma unroll
            for (int j = 0; j < TN; j++) rb[j] = Bs[kk][tx * TN + j];
#pragma unroll
            for (int i = 0; i < TM; i++)
#pragma unroll
                for (int j = 0; j < TN; j++) acc[i][j] += ra[i] * rb[j];
        }
        __syncthreads();
    }
#pragma unroll
    for (int i = 0; i < TM; i++) {
        int r = rowBase + ty * TM + i;
        if (r < NN) {
            float4 v = make_float4(acc[i][0], acc[i][1], acc[i][2], acc[i][3]);
            *(float4*)(C + (size_t)r * HC + colBase + tx * TN) = v;
        }
    }
}

// ---------------- per-node attention logits ----------------
__global__ void k_s(const float* __restrict__ asrc, const float* __restrict__ adst) {
    int n = blockIdx.x;
    int t = threadIdx.x;
    __shared__ float ss[256], sd[256];
    float v = g_h[(size_t)n * HC + t];
    ss[t] = v * asrc[t];
    sd[t] = v * adst[t];
    __syncthreads();
    for (int st = 32; st > 0; st >>= 1) {
        if ((t & 63) < st) {
            ss[t] += ss[t + st];
            sd[t] += sd[t + st];
        }
        __syncthreads();
    }
    if ((t & 63) == 0) {
        int hh = t >> 6;
        g_ssrc[n * 4 + hh] = ss[t];
        g_sdst[n * 4 + hh] = sd[t];
    }
}

// ---------------- warp-per-dst-node softmax + aggregation ----------------
template <bool L0>
__global__ __launch_bounds__(256) void k_agg(const float* __restrict__ bias,
                                             float* __restrict__ out) {
    int w = (blockIdx.x * blockDim.x + threadIdx.x) >> 5;
    int lane = threadIdx.x & 31;
    if (w >= NN) return;
    int n = w;
    int start = g_rowptr[n], end = g_rowptr[n + 1];
    float4 sdv = *(const float4*)&g_sdst[n * 4];
    float4 ssv = *(const float4*)&g_ssrc[n * 4];
    float sd0 = sdv.x, sd1 = sdv.y, sd2 = sdv.z, sd3 = sdv.w;
    float as0 = ssv.x + sd0, as1 = ssv.y + sd1, as2 = ssv.z + sd2, as3 = ssv.w + sd3;
    if (L0) {
        as0 += g_selfAE[0];
        as1 += g_selfAE[1];
        as2 += g_selfAE[2];
        as3 += g_selfAE[3];
    }
    float a0s = lrelu(as0), a1s = lrelu(as1), a2s = lrelu(as2), a3s = lrelu(as3);
    float m0 = a0s, m1 = a1s, m2 = a2s, m3 = a3s;
    // pass 1: per-head max (edges split over lanes)
    for (int e = start + lane; e < end; e += 32) {
        int s = g_csrc[e];
        float4 av = *(const float4*)&g_ssrc[s * 4];
        float b0 = av.x + sd0, b1 = av.y + sd1, b2 = av.z + sd2, b3 = av.w + sd3;
        if (L0) {
            float4 ev = *(const float4*)&g_alphaE[(size_t)g_ceid[e] * 4];
            b0 += ev.x; b1 += ev.y; b2 += ev.z; b3 += ev.w;
        }
        m0 = fmaxf(m0, lrelu(b0));
        m1 = fmaxf(m1, lrelu(b1));
        m2 = fmaxf(m2, lrelu(b2));
        m3 = fmaxf(m3, lrelu(b3));
    }
#pragma unroll
    for (int off = 16; off; off >>= 1) {
        m0 = fmaxf(m0, __shfl_xor_sync(0xffffffffu, m0, off));
        m1 = fmaxf(m1, __shfl_xor_sync(0xffffffffu, m1, off));
        m2 = fmaxf(m2, __shfl_xor_sync(0xffffffffu, m2, off));
        m3 = fmaxf(m3, __shfl_xor_sync(0xffffffffu, m3, off));
    }
    // pass 2: accumulate (all lanes cooperate per edge, lane = channel slice)
    float acc0 = 0.f, acc1 = 0.f, acc2 = 0.f, acc3 = 0.f;
    float acc4 = 0.f, acc5 = 0.f, acc6 = 0.f, acc7 = 0.f;
    float d0 = 0.f, d1 = 0.f, d2 = 0.f, d3 = 0.f;
    {
        float w0 = expf(a0s - m0), w1 = expf(a1s - m1);
        float w2 = expf(a2s - m2), w3 = expf(a3s - m3);
        d0 += w0; d1 += w1; d2 += w2; d3 += w3;
        const float* hr = &g_h[(size_t)n * HC + lane];
        acc0 += w0 * hr[0];   acc1 += w0 * hr[32];
        acc2 += w1 * hr[64];  acc3 += w1 * hr[96];
        acc4 += w2 * hr[128]; acc5 += w2 * hr[160];
        acc6 += w3 * hr[192]; acc7 += w3 * hr[224];
    }
    for (int e = start; e < end; e++) {
        int s = g_csrc[e];
        float4 av = *(const float4*)&g_ssrc[s * 4];
        float b0 = av.x + sd0, b1 = av.y + sd1, b2 = av.z + sd2, b3 = av.w + sd3;
        if (L0) {
            float4 ev = *(const float4*)&g_alphaE[(size_t)g_ceid[e] * 4];
            b0 += ev.x; b1 += ev.y; b2 += ev.z; b3 += ev.w;
        }
        float w0 = expf(lrelu(b0) - m0), w1 = expf(lrelu(b1) - m1);
        float w2 = expf(lrelu(b2) - m2), w3 = expf(lrelu(b3) - m3);
        d0 += w0; d1 += w1; d2 += w2; d3 += w3;
        const float* hr = &g_h[(size_t)s * HC + lane];
        acc0 += w0 * hr[0];   acc1 += w0 * hr[32];
        acc2 += w1 * hr[64];  acc3 += w1 * hr[96];
        acc4 += w2 * hr[128]; acc5 += w2 * hr[160];
        acc6 += w3 * hr[192]; acc7 += w3 * hr[224];
    }
    float i0 = 1.f / (d0 + 1e-16f), i1 = 1.f / (d1 + 1e-16f);
    float i2 = 1.f / (d2 + 1e-16f), i3 = 1.f / (d3 + 1e-16f);
    size_t base = (size_t)n * HC + lane;
    out[base + 0]   = acc0 * i0 + bias[lane + 0];
    out[base + 32]  = acc1 * i0 + bias[lane + 32];
    out[base + 64]  = acc2 * i1 + bias[lane + 64];
    out[base + 96]  = acc3 * i1 + bias[lane + 96];
    out[base + 128] = acc4 * i2 + bias[lane + 128];
    out[base + 160] = acc5 * i2 + bias[lane + 160];
    out[base + 192] = acc6 * i3 + bias[lane + 192];
    out[base + 224] = acc7 * i3 + bias[lane + 224];
}

// ---------------- BatchNorm + ReLU ----------------
__global__ void k_zerobn() {
    int t = threadIdx.x;
    g_bnsum[t] = 0.0;
    g_bnsq[t] = 0.0;
}

__global__ void k_bnstats(const float* __restrict__ buf) {
    int t = threadIdx.x;
    int r0 = blockIdx.x * 256;
    int r1 = min(NN, r0 + 256);
    float s = 0.f, s2 = 0.f;
    for (int r = r0; r < r1; r++) {
        float v = buf[(size_t)r * HC + t];
        s += v;
        s2 += v * v;
    }
    atomicAdd(&g_bnsum[t], (double)s);
    atomicAdd(&g_bnsq[t], (double)s2);
}

__global__ void k_bnfin(const float* __restrict__ gamma, const float* __restrict__ beta) {
    int c = threadIdx.x;
    double mu = g_bnsum[c] / (double)NN;
    double var = g_bnsq[c] / (double)NN - mu * mu;
    float inv = (float)(1.0 / sqrt(var + (double)BNEPS));
    float sc = gamma[c] * inv;
    g_scale[c] = sc;
    g_shift[c] = beta[c] - (float)mu * sc;
}

__global__ void k_bnapply(float* __restrict__ buf) {
    size_t i = (size_t)blockIdx.x * 256 + threadIdx.x;
    if (i < (size_t)NN * HC) {
        int c = (int)(i & 255);
        float v = buf[i] * g_scale[c] + g_shift[c];
        buf[i] = v > 0.f ? v : 0.f;
    }
}

// ---------------- pooling ----------------
__global__ void k_pool(const float* __restrict__ buf, const int* __restrict__ batch) {
    int t = threadIdx.x;
    int r0 = blockIdx.x * 128;
    if (r0 >= NN) return;
    int r1 = min(NN, r0 + 128);
    int cur = batch[r0];
    float acc = 0.f, cnt = 0.f;
    for (int r = r0; r < r1; r++) {
        int b = batch[r];
        if (b != cur) {
            atomicAdd(&g_pool[cur * HC + t], acc);
            if (t == 0) atomicAdd(&g_cnt[cur], cnt);
            acc = 0.f;
            cnt = 0.f;
            cur = b;
        }
        acc += buf[(size_t)r * HC + t];
        cnt += 1.f;
    }
    atomicAdd(&g_pool[cur * HC + t], acc);
    if (t == 0) atomicAdd(&g_cnt[cur], cnt);
}

__global__ void k_final(float* __restrict__ out) {
    int i = blockIdx.x * 256 + threadIdx.x;  // G*HC = 65536
    int g = i >> 8;
    float c = g_cnt[g];
    c = c < 1.f ? 1.f : c;
    out[i] = g_pool[i] / c;
}

// ---------------- host driver ----------------
extern "C" void kernel_launch(void* const* d_in, const int* in_sizes, int n_in,
                              void* d_out, int out_size) {
    const float* x = (const float*)d_in[0];
    const int* ei = (const int*)d_in[1];
    const float* ea = (const float*)d_in[2];
    const int* batch = (const int*)d_in[3];
    const float* W[3]    = {(const float*)d_in[4],  (const float*)d_in[10], (const float*)d_in[16]};
    const float* asrc[3] = {(const float*)d_in[5],  (const float*)d_in[11], (const float*)d_in[17]};
    const float* adst[3] = {(const float*)d_in[6],  (const float*)d_in[12], (const float*)d_in[18]};
    const float* bias[3] = {(const float*)d_in[7],  (const float*)d_in[13], (const float*)d_in[19]};
    const float* gam[3]  = {(const float*)d_in[8],  (const float*)d_in[14], (const float*)d_in[20]};
    const float* bet[3]  = {(const float*)d_in[9],  (const float*)d_in[15], (const float*)d_in[21]};
    const float* We0 = (const float*)d_in[22];
    const float* atte = (const float*)d_in[23];
    const int* src = ei;
    const int* dst = ei + EE;
    float* out = (float*)d_out;

    float* hbuf;
    cudaGetSymbolAddress((void**)&hbuf, g_h);
    float* bufA;
    cudaGetSymbolAddress((void**)&bufA, g_bufA);
    float* bufB;
    cudaGetSymbolAddress((void**)&bufB, g_bufB);

    const int EB = (EE + 255) / 256;  // 3125

    k_init<<<256, 256>>>();
    k_hist<<<EB, 256>>>(dst);
    k_scan<<<1, 1024>>>();
    k_scatter<<<EB, 256>>>(src, dst);
    k_ea_sum<<<256, 256>>>(ea);
    k_M<<<1, 64>>>(We0, atte);
    k_alphaE<<<EB, 256>>>(ea);

    dim3 gemmGrid(HC / BN, (NN + BM - 1) / BM);
    const int aggB = (NN + 7) / 8;     // 8 warps/block
    const int elemB = (NN * HC) / 256; // 50000

    // ---- layer 0 ----
    k_sgemm<<<gemmGrid, 256>>>(x, W[0], hbuf, FEAT);
    k_s<<<NN, 256>>>(asrc[0], adst[0]);
    k_agg<true><<<aggB, 256>>>(bias[0], bufA);
    k_zerobn<<<1, 256>>>();
    k_bnstats<<<(NN + 255) / 256, 256>>>(bufA);
    k_bnfin<<<1, 256>>>(gam[0], bet[0]);
    k_bnapply<<<elemB, 256>>>(bufA);

    // ---- layer 1 ----
    k_sgemm<<<gemmGrid, 256>>>(bufA, W[1], hbuf, HC);
    k_s<<<NN, 256>>>(asrc[1], adst[1]);
    k_agg<false><<<aggB, 256>>>(bias[1], bufB);
    k_zerobn<<<1, 256>>>();
    k_bnstats<<<(NN + 255) / 256, 256>>>(bufB);
    k_bnfin<<<1, 256>>>(gam[1], bet[1]);
    k_bnapply<<<elemB, 256>>>(bufB);

    // ---- layer 2 ----
    k_sgemm<<<gemmGrid, 256>>>(bufB, W[2], hbuf, HC);
    k_s<<<NN, 256>>>(asrc[2], adst[2]);
    k_agg<false><<<aggB, 256>>>(bias[2], bufA);
    k_zerobn<<<1, 256>>>();
    k_bnstats<<<(NN + 255) / 256, 256>>>(bufA);
    k_bnfin<<<1, 256>>>(gam[2], bet[2]);
    k_bnapply<<<elemB, 256>>>(bufA);

    // ---- pool ----
    k_pool<<<(NN + 127) / 128, 256>>>(bufA, batch);
    k_final<<<GG, 256>>>(out);
}